// round 16
// baseline (speedup 1.0000x reference)
#include <cuda_runtime.h>
#include <cuda_fp16.h>
#include <math.h>
#include <stdint.h>

#define BTOT 2048
#define NTRAIN 50000
#define NPAD 50048
#define BN 128
#define NCH 391            // NPAD / BN
#define NSPLIT 18
#define CDIM 16
#define MT 256

// exp(-d/(2*sigma^2)) = 2^( K1*(x.t) + K2*xsq + K2*tsq ); A pre-scaled by K1,
// norm terms folded into 4 augmented k-slots.
#define K1f 0.014426950408889634f     //  0.01  * log2(e)
#define K2f (-0.0072134752044448170f) // -0.005 * log2(e)

// ---------------- device scratch ----------------
__device__ __align__(16) __half g_txb[(size_t)NPAD * 64];   // trx fp16
__device__ __align__(16) __half g_taux[(size_t)NPAD * 8];   // [1,1,tsqK2hi,tsqK2lo,0..]
__device__ __align__(16) __half g_xh[(size_t)BTOT * 64];    // x * K1 fp16
__device__ __align__(16) __half g_xaux[(size_t)BTOT * 8];   // [xsqK2hi,xsqK2lo,1,1,0..]
__device__ __align__(16) __half g_tyhi[(size_t)CDIM * NPAD];
__device__ float g_pp[NSPLIT * BTOT * CDIM];
__device__ float g_ws[NSPLIT * BTOT];

// ---------------- helpers ----------------
static __device__ __forceinline__ uint32_t s2u(const void* p) {
    uint32_t a;
    asm("{ .reg .u64 t; cvta.to.shared.u64 t, %1; cvt.u32.u64 %0, t; }" : "=r"(a) : "l"(p));
    return a;
}
static __device__ __forceinline__ void cpa16(uint32_t dst, const void* src) {
    asm volatile("cp.async.cg.shared.global [%0], [%1], 16;" :: "r"(dst), "l"(src));
}
static __device__ __forceinline__ void cpcommit() { asm volatile("cp.async.commit_group;"); }
static __device__ __forceinline__ void cpwait0() { asm volatile("cp.async.wait_group 0;"); }

static __device__ __forceinline__ void ldsm4(uint32_t* r, uint32_t addr) {
    asm volatile("ldmatrix.sync.aligned.m8n8.x4.shared.b16 {%0,%1,%2,%3}, [%4];"
                 : "=r"(r[0]), "=r"(r[1]), "=r"(r[2]), "=r"(r[3]) : "r"(addr));
}
static __device__ __forceinline__ void ldsm2(uint32_t* r, uint32_t addr) {
    asm volatile("ldmatrix.sync.aligned.m8n8.x2.shared.b16 {%0,%1}, [%2];"
                 : "=r"(r[0]), "=r"(r[1]) : "r"(addr));
}
static __device__ __forceinline__ void mma16816(float* d, const uint32_t* a,
                                                uint32_t b0, uint32_t b1) {
    asm volatile(
        "mma.sync.aligned.m16n8k16.row.col.f32.f16.f16.f32 "
        "{%0,%1,%2,%3}, {%4,%5,%6,%7}, {%8,%9}, {%0,%1,%2,%3};"
        : "+f"(d[0]), "+f"(d[1]), "+f"(d[2]), "+f"(d[3])
        : "r"(a[0]), "r"(a[1]), "r"(a[2]), "r"(a[3]), "r"(b0), "r"(b1));
}
static __device__ __forceinline__ void mma16808(float* d, uint32_t a0, uint32_t a1,
                                                uint32_t b0) {
    asm volatile(
        "mma.sync.aligned.m16n8k8.row.col.f32.f16.f16.f32 "
        "{%0,%1,%2,%3}, {%4,%5}, {%6}, {%0,%1,%2,%3};"
        : "+f"(d[0]), "+f"(d[1]), "+f"(d[2]), "+f"(d[3])
        : "r"(a0), "r"(a1), "r"(b0));
}
static __device__ __forceinline__ uint32_t pack_hf(float hi, float lo) {
    uint32_t r; asm("cvt.rn.f16x2.f32 %0, %1, %2;" : "=r"(r) : "f"(hi), "f"(lo));
    return r;
}
static __device__ __forceinline__ uint32_t ex2h2(uint32_t a) {
    uint32_t r; asm("ex2.approx.f16x2 %0, %1;" : "=r"(r) : "r"(a));
    return r;
}
static __device__ __forceinline__ uint32_t h2bits(__half2 h) {
    uint32_t r; asm("mov.b32 %0, %1;" : "=r"(r) : "r"(*(uint32_t*)&h));
    return r;
}

#define SW(o) ((uint32_t)(o) ^ ((((uint32_t)(o)) >> 3) & 0x70u))

// smem layout (bytes)
#define OFF_X   0       // 32K  x main tile (256 rows)
#define OFF_XA  32768   // 4K   x aux tile
#define OFF_T   36864   // 2 x 16K t main
#define OFF_TA  69632   // 2 x 2K  t aux
#define OFF_Y   73728   // 2 x 4K  Y (fp16)
#define SMEM_SZ 81920

// =====================================================================
// Merged precompute, MLP=8: 2 threads/row, 8 contiguous float4 loads
// =====================================================================
#define NB_T ((NPAD * 2) / 256)          // 391
#define NB_X ((BTOT * 2) / 256)          // 16
#define NB_Y ((NPAD + 255) / 256)        // 196

__global__ void k_pre(const float* __restrict__ trx, const float* __restrict__ x,
                      const float* __restrict__ trY) {
    __shared__ __half shi[16][256];
    int bx = blockIdx.x;
    int t = threadIdx.x;
    if (bx < NB_T + NB_X) {
        const bool isx = (bx >= NB_T);
        int gid = (isx ? (bx - NB_T) : bx) * 256 + t;
        int row = gid >> 1, q = gid & 1;
        const float* src = isx ? (x + (size_t)row * 64 + q * 32)
                               : (trx + (size_t)row * 64 + q * 32);
        const bool valid = isx || (row < NTRAIN);
        // 8 independent float4 loads (MLP = 8), fully contiguous per thread
        float4 v[8];
#pragma unroll
        for (int i = 0; i < 8; i++) v[i] = make_float4(0.f, 0.f, 0.f, 0.f);
        if (valid) {
#pragma unroll
            for (int i = 0; i < 8; i++) v[i] = *(const float4*)(src + i * 4);
        }
        float ss = 0.f;
#pragma unroll
        for (int i = 0; i < 8; i++)
            ss += v[i].x * v[i].x + v[i].y * v[i].y + v[i].z * v[i].z + v[i].w * v[i].w;
        const float sc = isx ? K1f : 1.f;
        __half* dstm = (isx ? g_xh : g_txb) + (size_t)row * 64 + q * 32;
#pragma unroll
        for (int p = 0; p < 4; p++) {
            uint4 s0;
            s0.x = h2bits(__floats2half2_rn(v[2 * p].x * sc, v[2 * p].y * sc));
            s0.y = h2bits(__floats2half2_rn(v[2 * p].z * sc, v[2 * p].w * sc));
            s0.z = h2bits(__floats2half2_rn(v[2 * p + 1].x * sc, v[2 * p + 1].y * sc));
            s0.w = h2bits(__floats2half2_rn(v[2 * p + 1].z * sc, v[2 * p + 1].w * sc));
            *(uint4*)(dstm + p * 8) = s0;
        }
        // norm reduce across the 2 lanes of this row
        ss += __shfl_xor_sync(0xffffffffu, ss, 1, 2);
        if (q == 0) {
            if (isx) {
                float xq = ss * K2f;
                __half hi = __float2half_rn(xq);
                __half lo = __float2half_rn(xq - __half2float(hi));
                __half2* dst = (__half2*)(g_xaux + (size_t)row * 8);
                dst[0] = __halves2half2(hi, lo);
                dst[1] = __floats2half2_rn(1.f, 1.f);
                dst[2] = __floats2half2_rn(0.f, 0.f);
                dst[3] = __floats2half2_rn(0.f, 0.f);
            } else {
                __half hi, lo;
                if (valid) {
                    float tq = ss * K2f;
                    hi = __float2half_rn(tq);
                    lo = __float2half_rn(tq - __half2float(hi));
                } else {
                    hi = __float2half_rn(-60000.f);  // pad rows -> weight 0
                    lo = __float2half_rn(0.f);
                }
                __half2* dst = (__half2*)(g_taux + (size_t)row * 8);
                dst[0] = __floats2half2_rn(1.f, 1.f);
                dst[1] = __halves2half2(hi, lo);
                dst[2] = __floats2half2_rn(0.f, 0.f);
                dst[3] = __floats2half2_rn(0.f, 0.f);
            }
        }
    } else {
        int n0 = (bx - NB_T - NB_X) * 256;
#pragma unroll
        for (int it = 0; it < 16; it++) {
            int e = t + it * 256;
            int r = e >> 4, c = e & 15;
            int row = n0 + r;
            float v = (row < NTRAIN) ? trY[(size_t)row * 16 + c] : 0.f;
            shi[c][r] = __float2half_rn(v);
        }
        __syncthreads();
        if (n0 + t < NPAD) {
#pragma unroll
            for (int c = 0; c < 16; c++)
                g_tyhi[(size_t)c * NPAD + n0 + t] = shi[c][t];
        }
    }
}

// =====================================================================
// Main: MT=256, np-level software pipeline (GEMM1[np+1] before epi[np])
// =====================================================================
__global__ void __launch_bounds__(256, 1) k_main() {
    extern __shared__ char smem[];
    const uint32_t sb = s2u(smem);
    const int t = threadIdx.x;
    const int wid = t >> 5, lane = t & 31;
    const int mbase = blockIdx.x * MT;
    const int s = blockIdx.y;

    // ldmatrix lane mapping
    const int l8 = lane & 7, lq = lane >> 3;
    const int lr = l8 + ((lq & 1) << 3);  // row within 16
    const int lh = lq >> 1;               // 16B column half

    // ones B-fragment for the weight-sum column (n=0 all-ones, others 0)
    const uint32_t bones = (lane < 4) ? 0x3C003C00u : 0u;

    // ---- prologue: x main (256 rows) + x aux ----
#pragma unroll
    for (int i = 0; i < 8; i++) {
        int e = t + i * 256;
        int row = e >> 3, u = e & 7;
        cpa16(sb + OFF_X + SW(row * 128 + u * 16),
              g_xh + (size_t)(mbase + row) * 64 + u * 8);
    }
    cpa16(sb + OFF_XA + t * 16, g_xaux + (size_t)(mbase + t) * 8);

    auto load_chunk = [&](int ch, int b) {
        int nb = ch * BN;
#pragma unroll
        for (int i = 0; i < 4; i++) {
            int e = t + i * 256;
            int row = e >> 3, u = e & 7;
            cpa16(sb + OFF_T + b * 16384 + SW(row * 128 + u * 16),
                  g_txb + (size_t)(nb + row) * 64 + u * 8);
        }
        if (t < 128)
            cpa16(sb + OFF_TA + b * 2048 + t * 16, g_taux + (size_t)(nb + t) * 8);
        {
            int nblk = t >> 4, c = t & 15;
            cpa16(sb + OFF_Y + b * 4096 + c * 256 + (((uint32_t)(nblk ^ c)) << 4),
                  g_tyhi + (size_t)c * NPAD + nb + nblk * 8);
        }
    };
    load_chunk(s, 0);
    cpcommit();
    cpwait0();
    __syncthreads();

    // ---- hoist A fragments: 2 m-tiles x 4 k16, + aux via one ldsm4 ----
    uint32_t ax[2][4][4], axa[4];
#pragma unroll
    for (int mm = 0; mm < 2; mm++)
#pragma unroll
        for (int kt = 0; kt < 4; kt++) {
            uint32_t o = SW((wid * 32 + mm * 16 + lr) * 128 + kt * 32 + lh * 16);
            ldsm4(ax[mm][kt], sb + OFF_X + o);
        }
    ldsm4(axa, sb + OFF_XA + ((wid * 32 + lane) << 4));

    float acc0[2][4], acc1[2][4], acc2[2][4];
#pragma unroll
    for (int mm = 0; mm < 2; mm++)
#pragma unroll
        for (int q = 0; q < 4; q++) { acc0[mm][q] = 0.f; acc1[mm][q] = 0.f; acc2[mm][q] = 0.f; }

    for (int ch = s, jj = 0; ch < NCH; ch += NSPLIT, jj++) {
        const int b = jj & 1;
        if (ch + NSPLIT < NCH) load_chunk(ch + NSPLIT, b ^ 1);
        cpcommit();

        const uint32_t tb = sb + OFF_T + b * 16384;
        const uint32_t tab = sb + OFF_TA + b * 2048;
        const uint32_t yb = sb + OFF_Y + b * 4096;

        // GEMM1 into c-buffer [buf][mm][jn][q]
        float cb[2][2][2][4];
        auto do_gemm1 = [&](int np, int buf) {
#pragma unroll
            for (int mm = 0; mm < 2; mm++)
#pragma unroll
                for (int jn = 0; jn < 2; jn++)
#pragma unroll
                    for (int q = 0; q < 4; q++) cb[buf][mm][jn][q] = 0.f;
#pragma unroll
            for (int kt = 0; kt < 4; kt++) {
                uint32_t bt[4];
                ldsm4(bt, tb + SW((np * 16 + lr) * 128 + kt * 32 + lh * 16));
#pragma unroll
                for (int mm = 0; mm < 2; mm++) {
                    mma16816(cb[buf][mm][0], ax[mm][kt], bt[0], bt[2]);
                    mma16816(cb[buf][mm][1], ax[mm][kt], bt[1], bt[3]);
                }
            }
            {
                uint32_t bta[2];
                ldsm2(bta, tab + ((np * 16 + (lane & 15)) << 4));
#pragma unroll
                for (int mm = 0; mm < 2; mm++) {
                    mma16808(cb[buf][mm][0], axa[mm * 2], axa[mm * 2 + 1], bta[0]);
                    mma16808(cb[buf][mm][1], axa[mm * 2], axa[mm * 2 + 1], bta[1]);
                }
            }
        };

        do_gemm1(0, 0);
#pragma unroll
        for (int np = 0; np < 8; np++) {
            // issue next tile's GEMM1 first: independent tensor work that
            // overlaps the cvt/ex2/GEMM2 dependency chain of this tile
            if (np < 7) do_gemm1(np + 1, (np + 1) & 1);
            const int buf = np & 1;
            uint32_t bh[4];
            {
                uint32_t col = (uint32_t)((2 * np + lh) ^ lr) << 4;
                ldsm4(bh, yb + lr * 256 + col);
            }
#pragma unroll
            for (int mm = 0; mm < 2; mm++) {
                uint32_t ah[4];
#pragma unroll
                for (int jn = 0; jn < 2; jn++) {
                    ah[jn * 2 + 0] = ex2h2(pack_hf(cb[buf][mm][jn][1], cb[buf][mm][jn][0]));
                    ah[jn * 2 + 1] = ex2h2(pack_hf(cb[buf][mm][jn][3], cb[buf][mm][jn][2]));
                }
                mma16816(acc0[mm], ah, bh[0], bh[2]);
                mma16816(acc1[mm], ah, bh[1], bh[3]);
                mma16816(acc2[mm], ah, bones, bones);
            }
        }

        cpwait0();
        __syncthreads();
    }

    // ---- store pred partials + weight sums ----
    const int cc = 2 * (lane & 3);
#pragma unroll
    for (int mm = 0; mm < 2; mm++) {
        int rr = mbase + wid * 32 + mm * 16 + (lane >> 2);
        float* p0 = g_pp + ((size_t)s * BTOT + rr) * CDIM;
        float* p1 = p0 + 8 * CDIM;
        *(float2*)(p0 + cc) = make_float2(acc0[mm][0], acc0[mm][1]);
        *(float2*)(p0 + 8 + cc) = make_float2(acc1[mm][0], acc1[mm][1]);
        *(float2*)(p1 + cc) = make_float2(acc0[mm][2], acc0[mm][3]);
        *(float2*)(p1 + 8 + cc) = make_float2(acc1[mm][2], acc1[mm][3]);
        if ((lane & 3) == 0) {
            g_ws[s * BTOT + rr] = acc2[mm][0];
            g_ws[s * BTOT + rr + 8] = acc2[mm][2];
        }
    }
}

// =====================================================================
// Reduce N-split partials + normalize
// =====================================================================
__global__ void k_fin(float* __restrict__ out) {
    int i = blockIdx.x * blockDim.x + threadIdx.x;
    if (i >= BTOT * CDIM) return;
    int qd = i >> 4;
    float acc = 0.f, wsum = 0.f;
#pragma unroll
    for (int s = 0; s < NSPLIT; s++) {
        acc += g_pp[(size_t)s * BTOT * CDIM + i];
        wsum += g_ws[s * BTOT + qd];
    }
    out[i] = acc / (wsum + 1e-10f);
}

extern "C" void kernel_launch(void* const* d_in, const int* in_sizes, int n_in,
                              void* d_out, int out_size) {
    const float* x   = (const float*)d_in[0];
    const float* trx = (const float*)d_in[1];
    const float* trY = (const float*)d_in[2];
    float* out = (float*)d_out;

    cudaFuncSetAttribute(k_main, cudaFuncAttributeMaxDynamicSharedMemorySize, SMEM_SZ);

    k_pre<<<NB_T + NB_X + NB_Y, 256>>>(trx, x, trY);
    dim3 grid(BTOT / MT, NSPLIT);
    k_main<<<grid, 256, SMEM_SZ>>>();
    k_fin<<<(BTOT * CDIM + 255) / 256, 256>>>(out);
}

// round 17
// speedup vs baseline: 1.0877x; 1.0877x over previous
#include <cuda_runtime.h>
#include <cuda_fp16.h>
#include <math.h>
#include <stdint.h>

#define BTOT 2048
#define NTRAIN 50000
#define NPAD 50176         // 196 * 256
#define BN 256
#define NCH 196            // NPAD / BN
#define NSPLIT 18
#define CDIM 16
#define MT 256

// exp(-d/(2*sigma^2)) = 2^( K1*(x.t) + K2*xsq + K2*tsq ); A pre-scaled by K1,
// norm terms folded into 4 augmented k-slots.
#define K1f 0.014426950408889634f     //  0.01  * log2(e)
#define K2f (-0.0072134752044448170f) // -0.005 * log2(e)

// ---------------- device scratch ----------------
__device__ __align__(16) __half g_txb[(size_t)NPAD * 64];   // trx fp16
__device__ __align__(16) __half g_taux[(size_t)NPAD * 8];   // [1,1,tsqK2hi,tsqK2lo,0..]
__device__ __align__(16) __half g_xh[(size_t)BTOT * 64];    // x * K1 fp16
__device__ __align__(16) __half g_xaux[(size_t)BTOT * 8];   // [xsqK2hi,xsqK2lo,1,1,0..]
__device__ __align__(16) __half g_tyhi[(size_t)CDIM * NPAD];
__device__ float g_pp[NSPLIT * BTOT * CDIM];
__device__ float g_ws[NSPLIT * BTOT];

// ---------------- helpers ----------------
static __device__ __forceinline__ uint32_t s2u(const void* p) {
    uint32_t a;
    asm("{ .reg .u64 t; cvta.to.shared.u64 t, %1; cvt.u32.u64 %0, t; }" : "=r"(a) : "l"(p));
    return a;
}
static __device__ __forceinline__ void cpa16(uint32_t dst, const void* src) {
    asm volatile("cp.async.cg.shared.global [%0], [%1], 16;" :: "r"(dst), "l"(src));
}
static __device__ __forceinline__ void cpcommit() { asm volatile("cp.async.commit_group;"); }
static __device__ __forceinline__ void cpwait0() { asm volatile("cp.async.wait_group 0;"); }

static __device__ __forceinline__ void ldsm4(uint32_t* r, uint32_t addr) {
    asm volatile("ldmatrix.sync.aligned.m8n8.x4.shared.b16 {%0,%1,%2,%3}, [%4];"
                 : "=r"(r[0]), "=r"(r[1]), "=r"(r[2]), "=r"(r[3]) : "r"(addr));
}
static __device__ __forceinline__ void ldsm2(uint32_t* r, uint32_t addr) {
    asm volatile("ldmatrix.sync.aligned.m8n8.x2.shared.b16 {%0,%1}, [%2];"
                 : "=r"(r[0]), "=r"(r[1]) : "r"(addr));
}
static __device__ __forceinline__ void mma16816(float* d, const uint32_t* a,
                                                uint32_t b0, uint32_t b1) {
    asm volatile(
        "mma.sync.aligned.m16n8k16.row.col.f32.f16.f16.f32 "
        "{%0,%1,%2,%3}, {%4,%5,%6,%7}, {%8,%9}, {%0,%1,%2,%3};"
        : "+f"(d[0]), "+f"(d[1]), "+f"(d[2]), "+f"(d[3])
        : "r"(a[0]), "r"(a[1]), "r"(a[2]), "r"(a[3]), "r"(b0), "r"(b1));
}
static __device__ __forceinline__ void mma16808(float* d, uint32_t a0, uint32_t a1,
                                                uint32_t b0) {
    asm volatile(
        "mma.sync.aligned.m16n8k8.row.col.f32.f16.f16.f32 "
        "{%0,%1,%2,%3}, {%4,%5}, {%6}, {%0,%1,%2,%3};"
        : "+f"(d[0]), "+f"(d[1]), "+f"(d[2]), "+f"(d[3])
        : "r"(a0), "r"(a1), "r"(b0));
}
static __device__ __forceinline__ uint32_t pack_hf(float hi, float lo) {
    uint32_t r; asm("cvt.rn.f16x2.f32 %0, %1, %2;" : "=r"(r) : "f"(hi), "f"(lo));
    return r;
}
static __device__ __forceinline__ uint32_t ex2h2(uint32_t a) {
    uint32_t r; asm("ex2.approx.f16x2 %0, %1;" : "=r"(r) : "r"(a));
    return r;
}
static __device__ __forceinline__ uint32_t h2bits(__half2 h) {
    uint32_t r; asm("mov.b32 %0, %1;" : "=r"(r) : "r"(*(uint32_t*)&h));
    return r;
}

#define SW(o) ((uint32_t)(o) ^ ((((uint32_t)(o)) >> 3) & 0x70u))

// smem layout (bytes)
#define OFF_X   0       // 32K   x main tile (256 rows)
#define OFF_XA  32768   // 4K    x aux tile
#define OFF_T   36864   // 2 x 32K t main (256 rows/chunk)
#define OFF_TA  102400  // 2 x 4K  t aux
#define OFF_Y   110592  // 2 x 8K  Y (fp16, 256 n per chunk)
#define SMEM_SZ 126976

// =====================================================================
// Merged precompute, MLP=4 (best measured operating point)
// =====================================================================
#define NB_T ((NPAD * 4) / 256)          // 784
#define NB_X ((BTOT * 4) / 256)          // 32
#define NB_Y (NPAD / 256)                // 196

__global__ void k_pre(const float* __restrict__ trx, const float* __restrict__ x,
                      const float* __restrict__ trY) {
    __shared__ __half shi[16][256];
    int bx = blockIdx.x;
    int t = threadIdx.x;
    if (bx < NB_T + NB_X) {
        const bool isx = (bx >= NB_T);
        int gid = (isx ? (bx - NB_T) : bx) * 256 + t;
        int row = gid >> 2, q = gid & 3;
        const float* src = isx ? (x + (size_t)row * 64) : (trx + (size_t)row * 64);
        const bool valid = isx || (row < NTRAIN);
        // 4 independent float4 loads (MLP = 4), paired for contiguous stores
        float4 v[4];
#pragma unroll
        for (int i = 0; i < 4; i++) v[i] = make_float4(0.f, 0.f, 0.f, 0.f);
        if (valid) {
            v[0] = *(const float4*)(src + q * 8);
            v[1] = *(const float4*)(src + q * 8 + 4);
            v[2] = *(const float4*)(src + q * 8 + 32);
            v[3] = *(const float4*)(src + q * 8 + 36);
        }
        float ss = 0.f;
#pragma unroll
        for (int i = 0; i < 4; i++)
            ss += v[i].x * v[i].x + v[i].y * v[i].y + v[i].z * v[i].z + v[i].w * v[i].w;
        const float sc = isx ? K1f : 1.f;
        __half* dstm = (isx ? g_xh : g_txb) + (size_t)row * 64;
        uint4 s0, s1;
        s0.x = h2bits(__floats2half2_rn(v[0].x * sc, v[0].y * sc));
        s0.y = h2bits(__floats2half2_rn(v[0].z * sc, v[0].w * sc));
        s0.z = h2bits(__floats2half2_rn(v[1].x * sc, v[1].y * sc));
        s0.w = h2bits(__floats2half2_rn(v[1].z * sc, v[1].w * sc));
        s1.x = h2bits(__floats2half2_rn(v[2].x * sc, v[2].y * sc));
        s1.y = h2bits(__floats2half2_rn(v[2].z * sc, v[2].w * sc));
        s1.z = h2bits(__floats2half2_rn(v[3].x * sc, v[3].y * sc));
        s1.w = h2bits(__floats2half2_rn(v[3].z * sc, v[3].w * sc));
        *(uint4*)(dstm + q * 8) = s0;
        *(uint4*)(dstm + q * 8 + 32) = s1;
        // norm reduce across the 4 lanes of this row
        ss += __shfl_xor_sync(0xffffffffu, ss, 1, 4);
        ss += __shfl_xor_sync(0xffffffffu, ss, 2, 4);
        if (q == 0) {
            if (isx) {
                float xq = ss * K2f;
                __half hi = __float2half_rn(xq);
                __half lo = __float2half_rn(xq - __half2float(hi));
                __half2* dst = (__half2*)(g_xaux + (size_t)row * 8);
                dst[0] = __halves2half2(hi, lo);
                dst[1] = __floats2half2_rn(1.f, 1.f);
                dst[2] = __floats2half2_rn(0.f, 0.f);
                dst[3] = __floats2half2_rn(0.f, 0.f);
            } else {
                __half hi, lo;
                if (valid) {
                    float tq = ss * K2f;
                    hi = __float2half_rn(tq);
                    lo = __float2half_rn(tq - __half2float(hi));
                } else {
                    hi = __float2half_rn(-60000.f);  // pad rows -> weight 0
                    lo = __float2half_rn(0.f);
                }
                __half2* dst = (__half2*)(g_taux + (size_t)row * 8);
                dst[0] = __floats2half2_rn(1.f, 1.f);
                dst[1] = __halves2half2(hi, lo);
                dst[2] = __floats2half2_rn(0.f, 0.f);
                dst[3] = __floats2half2_rn(0.f, 0.f);
            }
        }
    } else {
        int n0 = (bx - NB_T - NB_X) * 256;
#pragma unroll
        for (int it = 0; it < 16; it++) {
            int e = t + it * 256;
            int r = e >> 4, c = e & 15;
            int row = n0 + r;
            float v = (row < NTRAIN) ? trY[(size_t)row * 16 + c] : 0.f;
            shi[c][r] = __float2half_rn(v);
        }
        __syncthreads();
        if (n0 + t < NPAD) {
#pragma unroll
            for (int c = 0; c < 16; c++)
                g_tyhi[(size_t)c * NPAD + n0 + t] = shi[c][t];
        }
    }
}

// =====================================================================
// Main: MT=256 warp-level m-doubling, BN=256 chunks (half the loop overhead)
// =====================================================================
__global__ void __launch_bounds__(256, 1) k_main() {
    extern __shared__ char smem[];
    const uint32_t sb = s2u(smem);
    const int t = threadIdx.x;
    const int wid = t >> 5, lane = t & 31;
    const int mbase = blockIdx.x * MT;
    const int s = blockIdx.y;

    // ldmatrix lane mapping
    const int l8 = lane & 7, lq = lane >> 3;
    const int lr = l8 + ((lq & 1) << 3);  // row within 16
    const int lh = lq >> 1;               // 16B column half

    // ones B-fragment for the weight-sum column (n=0 all-ones, others 0)
    const uint32_t bones = (lane < 4) ? 0x3C003C00u : 0u;

    // ---- prologue: x main (256 rows) + x aux ----
#pragma unroll
    for (int i = 0; i < 8; i++) {
        int e = t + i * 256;
        int row = e >> 3, u = e & 7;
        cpa16(sb + OFF_X + SW(row * 128 + u * 16),
              g_xh + (size_t)(mbase + row) * 64 + u * 8);
    }
    cpa16(sb + OFF_XA + t * 16, g_xaux + (size_t)(mbase + t) * 8);

    auto load_chunk = [&](int ch, int b) {
        int nb = ch * BN;
#pragma unroll
        for (int i = 0; i < 8; i++) {
            int e = t + i * 256;
            int row = e >> 3, u = e & 7;
            cpa16(sb + OFF_T + b * 32768 + SW(row * 128 + u * 16),
                  g_txb + (size_t)(nb + row) * 64 + u * 8);
        }
        cpa16(sb + OFF_TA + b * 4096 + t * 16, g_taux + (size_t)(nb + t) * 8);
#pragma unroll
        for (int i = 0; i < 2; i++) {
            int idx = t + i * 256;
            int nblk = idx >> 4, c = idx & 15;
            cpa16(sb + OFF_Y + b * 8192 + c * 512 + (((uint32_t)(nblk ^ c)) << 4),
                  g_tyhi + (size_t)c * NPAD + nb + nblk * 8);
        }
    };
    load_chunk(s, 0);
    cpcommit();
    cpwait0();
    __syncthreads();

    // ---- hoist A fragments: 2 m-tiles x 4 k16, + aux via one ldsm4 ----
    uint32_t ax[2][4][4], axa[4];
#pragma unroll
    for (int mm = 0; mm < 2; mm++)
#pragma unroll
        for (int kt = 0; kt < 4; kt++) {
            uint32_t o = SW((wid * 32 + mm * 16 + lr) * 128 + kt * 32 + lh * 16);
            ldsm4(ax[mm][kt], sb + OFF_X + o);
        }
    ldsm4(axa, sb + OFF_XA + ((wid * 32 + lane) << 4));

    float acc0[2][4], acc1[2][4], acc2[2][4];
#pragma unroll
    for (int mm = 0; mm < 2; mm++)
#pragma unroll
        for (int q = 0; q < 4; q++) { acc0[mm][q] = 0.f; acc1[mm][q] = 0.f; acc2[mm][q] = 0.f; }

    for (int ch = s, jj = 0; ch < NCH; ch += NSPLIT, jj++) {
        const int b = jj & 1;
        if (ch + NSPLIT < NCH) load_chunk(ch + NSPLIT, b ^ 1);
        cpcommit();

        const uint32_t tb = sb + OFF_T + b * 32768;
        const uint32_t tab = sb + OFF_TA + b * 4096;
        const uint32_t yb = sb + OFF_Y + b * 8192;

#pragma unroll
        for (int np = 0; np < 16; np++) {
            // ---- GEMM1 (augmented): c = log2-weight, 2 m-tiles share B ----
            float c[2][2][4];
#pragma unroll
            for (int mm = 0; mm < 2; mm++)
#pragma unroll
                for (int jn = 0; jn < 2; jn++)
#pragma unroll
                    for (int q = 0; q < 4; q++) c[mm][jn][q] = 0.f;
#pragma unroll
            for (int kt = 0; kt < 4; kt++) {
                uint32_t bt[4];
                ldsm4(bt, tb + SW((np * 16 + lr) * 128 + kt * 32 + lh * 16));
#pragma unroll
                for (int mm = 0; mm < 2; mm++) {
                    mma16816(c[mm][0], ax[mm][kt], bt[0], bt[2]);
                    mma16816(c[mm][1], ax[mm][kt], bt[1], bt[3]);
                }
            }
            {
                uint32_t bta[2];
                ldsm2(bta, tab + ((np * 16 + (lane & 15)) << 4));
#pragma unroll
                for (int mm = 0; mm < 2; mm++) {
                    mma16808(c[mm][0], axa[mm * 2], axa[mm * 2 + 1], bta[0]);
                    mma16808(c[mm][1], axa[mm * 2], axa[mm * 2 + 1], bta[1]);
                }
            }
            // ---- epilogue + GEMM2 + weight sum, B (Y) shared across m ----
            uint32_t bh[4];
            {
                uint32_t col = (uint32_t)((2 * np + lh) ^ lr) << 4;
                ldsm4(bh, yb + lr * 512 + col);
            }
#pragma unroll
            for (int mm = 0; mm < 2; mm++) {
                uint32_t ah[4];
#pragma unroll
                for (int jn = 0; jn < 2; jn++) {
                    ah[jn * 2 + 0] = ex2h2(pack_hf(c[mm][jn][1], c[mm][jn][0]));
                    ah[jn * 2 + 1] = ex2h2(pack_hf(c[mm][jn][3], c[mm][jn][2]));
                }
                mma16816(acc0[mm], ah, bh[0], bh[2]);
                mma16816(acc1[mm], ah, bh[1], bh[3]);
                mma16816(acc2[mm], ah, bones, bones);
            }
        }

        cpwait0();
        __syncthreads();
    }

    // ---- store pred partials + weight sums ----
    const int cc = 2 * (lane & 3);
#pragma unroll
    for (int mm = 0; mm < 2; mm++) {
        int rr = mbase + wid * 32 + mm * 16 + (lane >> 2);
        float* p0 = g_pp + ((size_t)s * BTOT + rr) * CDIM;
        float* p1 = p0 + 8 * CDIM;
        *(float2*)(p0 + cc) = make_float2(acc0[mm][0], acc0[mm][1]);
        *(float2*)(p0 + 8 + cc) = make_float2(acc1[mm][0], acc1[mm][1]);
        *(float2*)(p1 + cc) = make_float2(acc0[mm][2], acc0[mm][3]);
        *(float2*)(p1 + 8 + cc) = make_float2(acc1[mm][2], acc1[mm][3]);
        if ((lane & 3) == 0) {
            g_ws[s * BTOT + rr] = acc2[mm][0];
            g_ws[s * BTOT + rr + 8] = acc2[mm][2];
        }
    }
}

// =====================================================================
// Reduce N-split partials + normalize
// =====================================================================
__global__ void k_fin(float* __restrict__ out) {
    int i = blockIdx.x * blockDim.x + threadIdx.x;
    if (i >= BTOT * CDIM) return;
    int qd = i >> 4;
    float acc = 0.f, wsum = 0.f;
#pragma unroll
    for (int s = 0; s < NSPLIT; s++) {
        acc += g_pp[(size_t)s * BTOT * CDIM + i];
        wsum += g_ws[s * BTOT + qd];
    }
    out[i] = acc / (wsum + 1e-10f);
}

extern "C" void kernel_launch(void* const* d_in, const int* in_sizes, int n_in,
                              void* d_out, int out_size) {
    const float* x   = (const float*)d_in[0];
    const float* trx = (const float*)d_in[1];
    const float* trY = (const float*)d_in[2];
    float* out = (float*)d_out;

    cudaFuncSetAttribute(k_main, cudaFuncAttributeMaxDynamicSharedMemorySize, SMEM_SZ);

    k_pre<<<NB_T + NB_X + NB_Y, 256>>>(trx, x, trY);
    dim3 grid(BTOT / MT, NSPLIT);
    k_main<<<grid, 256, SMEM_SZ>>>();
    k_fin<<<(BTOT * CDIM + 255) / 256, 256>>>(out);
}